// round 11
// baseline (speedup 1.0000x reference)
#include <cuda_runtime.h>
#include <cstdint>

// ---------------- problem constants ----------------
#define BATCH   64
#define MAXH    64
#define MAXW    32
#define DIM     512
#define SGRID   8
#define HID     64

#define TPB       256
#define GRIDMAIN  444      // 3 CTAs/SM x 148 SMs — ALL resident (global barrier safe)
#define TSTRIDE   111      // GRIDMAIN / 4 quarters
#define QELEMS    (BATCH * MAXH * MAXW * DIM)
#define NROWS     (BATCH * MAXH)          // 4096 (b,i) row units

// SMEM layout (bytes) — quarter-N
#define OFF_W2    0        // w2 quarter [64 k][128 d] fp32    (32768)
#define OFF_HA    32768    // h buf0 [64 p][64 k] fp32         (16384)
#define OFF_HB    49152    // h buf1                           (16384)
#define OFF_B2    65536    // b2 quarter [128] fp32            (512)
#define OFF_M0    66048    // meta buf0: geom[64],addr[64],wy[64],wx[64] (1024)
#define OFF_M1    67072    // meta buf1                        (1024)
#define OFF_BASE  68096    // s_base[65]                       (260)
#define OFF_HW    68356    // s_hw[64]                         (256)
#define OFF_W1U   68612    // w1u[64]                          (256)
#define OFF_W1V   68868    // w1v[64]                          (256)
#define OFF_B1    69124    // b1[64]                           (256)
#define SMEM_BYTES 69632   // <= 75776 (227KB/3)

typedef unsigned long long ull;

// compacted h for active points: g_h[q*64 + k]
__device__ __align__(16) float g_h[BATCH * MAXH * MAXW * HID];
__device__ unsigned g_bar = 0;     // global barrier counter (rolling, never reset)

__device__ __forceinline__ float gelu_exact(float x) {
    return 0.5f * x * (1.0f + erff(x * 0.70710678118654752440f));
}

__device__ __forceinline__ ull dupf(float x) {
    ull r;
    unsigned xb = __float_as_uint(x);
    asm("mov.b64 %0, {%1, %1};" : "=l"(r) : "r"(xb));
    return r;
}

// zero/mask one (b,i) row unit
__device__ __forceinline__ void do_row(
    int r, const int* s_hw, float* __restrict__ out,
    float* __restrict__ mout, int tail, int tid)
{
    const int b = r >> 6, i = r & 63;
    const int hw = s_hw[b];
    const int H = hw >> 16, W = hw & 0xFFFF;
    float4* row = (float4*)(out + ((size_t)r) * (MAXW * DIM));
    const float4 z = make_float4(0.f, 0.f, 0.f, 0.f);
    if (i >= H) {
        #pragma unroll
        for (int e = 0; e < (MAXW * DIM / 4) / TPB; e++)   // 16 iters
            row[tid + TPB * e] = z;
    } else if (W < MAXW) {
        int start4 = W * (DIM / 4);
        int cnt4 = (MAXW - W) * (DIM / 4);
        for (int e = tid; e < cnt4; e += TPB)
            row[start4 + e] = z;
    }
    if (tail > 0 && tid < 32) {
        int idx = r * 32 + tid;
        if (idx < tail)
            mout[idx] = (i < H && tid < W) ? 1.0f : 0.0f;
    }
}

// ---------------- single fused persistent kernel ----------------
__global__ __launch_bounds__(TPB, 3) void hgq_all(
    const float* __restrict__ canonical,   // [8,8,512]
    const float* __restrict__ w1,          // [2,64]
    const float* __restrict__ b1,          // [64]
    const float* __restrict__ w2,          // [64,512]
    const float* __restrict__ b2,          // [512]
    const int*   __restrict__ th,
    const int*   __restrict__ tw,
    float*       __restrict__ out,         // [64,64,32,512] (+ mask tail)
    int          out_size)
{
    extern __shared__ char smem[];
    const float2* sb2 = (const float2*)(smem + OFF_B2);
    int*   s_base = (int*)(smem + OFF_BASE);   // [65]
    int*   s_hw   = (int*)(smem + OFF_HW);     // [64]
    float* s_w1u  = (float*)(smem + OFF_W1U);
    float* s_w1v  = (float*)(smem + OFF_W1V);
    float* s_b1   = (float*)(smem + OFF_B1);
    volatile unsigned* s_tgt = (unsigned*)(smem + OFF_M0);  // reuse meta buf pre-loop

    const int tid  = threadIdx.x;
    const int wid  = tid >> 5;
    const int nx   = tid & 31;
    const int qtr  = blockIdx.x & 3;
    const int t0   = blockIdx.x >> 2;
    const int tail = out_size - QELEMS;
    float* mout = out + QELEMS;

    // ---- one-time staging ----
    {
        const float* wsrc = w2 + qtr * 128;
        float4* ws = (float4*)(smem + OFF_W2);
        #pragma unroll
        for (int e = 0; e < 8; e++) {                  // 2048 float4
            int idx = tid + TPB * e;
            int k = idx >> 5, c4 = idx & 31;
            ws[idx] = __ldg((const float4*)(wsrc + k * DIM) + c4);
        }
        if (tid < 64)
            ((float2*)(smem + OFF_B2))[tid] = __ldg((const float2*)(b2 + qtr * 128) + tid);
        if (tid < 64) {
            s_w1u[tid] = __ldg(w1 + tid);
            s_w1v[tid] = __ldg(w1 + HID + tid);
            s_b1[tid]  = __ldg(b1 + tid);
            int H = min(max(__ldg(th + tid), 1), MAXH);
            int W = min(max(__ldg(tw + tid), 1), MAXW);
            s_hw[tid] = (H << 16) | W;
        }
    }
    __syncthreads();

    if (wid == 0) {
        int hw0 = s_hw[2 * nx], hw1 = s_hw[2 * nx + 1];
        int c0 = (hw0 >> 16) * (hw0 & 0xFFFF);
        int c1 = (hw1 >> 16) * (hw1 & 0xFFFF);
        int pair = c0 + c1, incl = pair;
        #pragma unroll
        for (int d = 1; d < 32; d <<= 1) {
            int n = __shfl_up_sync(0xFFFFFFFF, incl, d);
            if (nx >= d) incl += n;
        }
        s_base[2 * nx] = incl - pair;
        s_base[2 * nx + 1] = incl - c1;
        if (nx == 31) s_base[64] = incl;
    }
    __syncthreads();
    const int total = s_base[BATCH];

    // ================= PHASE A: gelu table slice =================
    for (int tt = blockIdx.x; tt * 64 < total; tt += GRIDMAIN) {
        int q = tt * 64 + (tid >> 2);
        if (q < total) {
            int lo = 0, hi = BATCH;
            while (hi - lo > 1) {
                int mid = (lo + hi) >> 1;
                if (q >= s_base[mid]) lo = mid; else hi = mid;
            }
            int hw = s_hw[lo];
            int H = hw >> 16, W = hw & 0xFFFF;
            int r = q - s_base[lo];
            int i = r / W, j = r - i * W;
            float u = (H > 1) ? (float)i / (float)(H - 1) : 0.0f;
            float v = (W > 1) ? (float)j / (float)(W - 1) : 0.0f;
            int kb = (tid & 3) * 16;
            float* dst = g_h + (size_t)q * HID + kb;
            #pragma unroll
            for (int c4 = 0; c4 < 4; c4++) {
                float4 o;
                o.x = gelu_exact(u * s_w1u[kb + c4 * 4 + 0] + v * s_w1v[kb + c4 * 4 + 0] + s_b1[kb + c4 * 4 + 0]);
                o.y = gelu_exact(u * s_w1u[kb + c4 * 4 + 1] + v * s_w1v[kb + c4 * 4 + 1] + s_b1[kb + c4 * 4 + 1]);
                o.z = gelu_exact(u * s_w1u[kb + c4 * 4 + 2] + v * s_w1v[kb + c4 * 4 + 2] + s_b1[kb + c4 * 4 + 2]);
                o.w = gelu_exact(u * s_w1u[kb + c4 * 4 + 3] + v * s_w1v[kb + c4 * 4 + 3] + s_b1[kb + c4 * 4 + 3]);
                *(float4*)(dst + c4 * 4) = o;
            }
        }
    }

    // ---- arrive at global barrier (g_h writes released) ----
    __threadfence();
    __syncthreads();
    if (tid == 0) {
        unsigned old = atomicAdd(&g_bar, 1u);
        s_tgt[0] = (old / GRIDMAIN + 1u) * GRIDMAIN;
    }
    __syncthreads();
    const unsigned bar_target = s_tgt[0];

    // ---- overlap with barrier wait: zero-fill + mask (independent of g_h) ----
    for (int r = blockIdx.x; r < NROWS; r += GRIDMAIN)
        do_row(r, s_hw, out, mout, tail, tid);
    if (blockIdx.x == 0 && tail > NROWS * 32) {
        for (int e = NROWS * 32 + tid; e < tail; e += TPB)
            mout[e] = 0.0f;
    }

    // ---- spin until all CTAs arrived ----
    if (tid == 0) {
        unsigned v;
        do {
            asm volatile("ld.global.acquire.gpu.u32 %0, [%1];"
                         : "=r"(v) : "l"(&g_bar) : "memory");
            if (v >= bar_target) break;
            __nanosleep(128);
        } while (true);
    }
    __syncthreads();

    // ================= PHASE B: GEMM + epilogue loop =================
    auto build = [&](int t, int sel) {
        float4* hbuf = (float4*)(smem + (sel ? OFF_HB : OFF_HA));
        char* mb = smem + (sel ? OFF_M1 : OFF_M0);
        int*   m_geom = (int*)mb;
        int*   m_addr = (int*)(mb + 256);
        float* m_wy   = (float*)(mb + 512);
        float* m_wx   = (float*)(mb + 768);

        const float4* src = (const float4*)(g_h + (size_t)t * 64 * HID);
        #pragma unroll
        for (int e = 0; e < 4; e++)
            hbuf[tid + TPB * e] = src[tid + TPB * e];

        if (tid < 64) {
            int q = t * 64 + tid;
            if (q < total) {
                int lo = 0, hi = BATCH;
                while (hi - lo > 1) {
                    int mid = (lo + hi) >> 1;
                    if (q >= s_base[mid]) lo = mid; else hi = mid;
                }
                int b = lo;
                int hw = s_hw[b];
                int H = hw >> 16, W = hw & 0xFFFF;
                int r = q - s_base[b];
                int i = r / W, j = r - i * W;
                float u = (H > 1) ? (float)i / (float)(H - 1) : 0.0f;
                float v = (W > 1) ? (float)j / (float)(W - 1) : 0.0f;
                float sy = fminf(u * (float)(SGRID - 1), (float)(SGRID - 1));
                float sx = fminf(v * (float)(SGRID - 1), (float)(SGRID - 1));
                int y0 = (int)sy, x0 = (int)sx;
                int y1 = min(y0 + 1, SGRID - 1);
                int x1 = min(x0 + 1, SGRID - 1);
                m_wy[tid] = sy - (float)y0;
                m_wx[tid] = sx - (float)x0;
                m_geom[tid] = y0 | (y1 << 8) | (x0 << 16) | (x1 << 24);
                m_addr[tid] = (b << 11) | (i << 5) | j;
            } else {
                m_wy[tid] = 0.f; m_wx[tid] = 0.f;
                m_geom[tid] = 0;
                m_addr[tid] = -1;
            }
        }
    };

    if (t0 * 64 < total) build(t0, 0);
    __syncthreads();

    int sel = 0;
    for (int t = t0; t * 64 < total; t += TSTRIDE) {
        const float* hbuf = (const float*)(smem + (sel ? OFF_HB : OFF_HA));
        const char* mb = smem + (sel ? OFF_M1 : OFF_M0);
        const int*   m_geom = (const int*)mb;
        const int*   m_addr = (const int*)(mb + 256);
        const float* m_wy   = (const float*)(mb + 512);
        const float* m_wx   = (const float*)(mb + 768);

        // ---- GEMM ----
        ull acc[8][2];
        #pragma unroll
        for (int pp = 0; pp < 8; pp++) { acc[pp][0] = 0ull; acc[pp][1] = 0ull; }

        const ull* shw2_u = (const ull*)(smem + OFF_W2);
        const int pbase = wid * 8;

        #pragma unroll 2
        for (int k = 0; k < HID; k += 2) {
            ull wv0[2], wv1[2];
            const ull* wk0 = shw2_u + k * 64;
            wv0[0] = wk0[nx];       wv0[1] = wk0[nx + 32];
            wv1[0] = wk0[64 + nx];  wv1[1] = wk0[64 + nx + 32];
            #pragma unroll
            for (int pp = 0; pp < 8; pp++) {
                float2 hv = *(const float2*)(hbuf + (pbase + pp) * HID + k);
                ull h0 = dupf(hv.x), h1 = dupf(hv.y);
                #pragma unroll
                for (int c = 0; c < 2; c++) {
                    asm("fma.rn.f32x2 %0, %1, %2, %3;"
                        : "=l"(acc[pp][c]) : "l"(h0), "l"(wv0[c]), "l"(acc[pp][c]));
                    asm("fma.rn.f32x2 %0, %1, %2, %3;"
                        : "=l"(acc[pp][c]) : "l"(h1), "l"(wv1[c]), "l"(acc[pp][c]));
                }
            }
        }

        // ---- epilogue ----
        {
            const float2* can2 = (const float2*)canonical + qtr * 64;
            float2 b2v[2];
            b2v[0] = sb2[nx]; b2v[1] = sb2[nx + 32];

            #pragma unroll
            for (int pp = 0; pp < 8; pp++) {
                int p = pbase + pp;
                int ad = m_addr[p];
                if (ad < 0) continue;
                int geom = m_geom[p];
                int y0 = geom & 0xFF, y1 = (geom >> 8) & 0xFF;
                int x0 = (geom >> 16) & 0xFF, x1 = (geom >> 24) & 0xFF;
                float wy = m_wy[p], wx = m_wx[p];
                const float2* p00 = can2 + (size_t)(y0 * SGRID + x0) * 256;
                const float2* p01 = can2 + (size_t)(y0 * SGRID + x1) * 256;
                const float2* p10 = can2 + (size_t)(y1 * SGRID + x0) * 256;
                const float2* p11 = can2 + (size_t)(y1 * SGRID + x1) * 256;
                float w00 = (1.f - wy) * (1.f - wx), w01 = (1.f - wy) * wx;
                float w10 = wy * (1.f - wx),         w11 = wy * wx;
                float* op = out + ((size_t)ad) * DIM + qtr * 128;

                #pragma unroll
                for (int c = 0; c < 2; c++) {
                    int dp = nx + 32 * c;
                    float2 q00 = __ldg(p00 + dp);
                    float2 q01 = __ldg(p01 + dp);
                    float2 q10 = __ldg(p10 + dp);
                    float2 q11 = __ldg(p11 + dp);
                    float bx = w00 * q00.x + w01 * q01.x + w10 * q10.x + w11 * q11.x;
                    float by = w00 * q00.y + w01 * q01.y + w10 * q10.y + w11 * q11.y;
                    ull A = acc[pp][c];
                    float2 r;
                    r.x = __uint_as_float((unsigned)A) + bx + b2v[c].x;
                    r.y = __uint_as_float((unsigned)(A >> 32)) + by + b2v[c].y;
                    *(float2*)(op + dp * 2) = r;
                }
            }
        }

        if ((t + TSTRIDE) * 64 < total) build(t + TSTRIDE, sel ^ 1);

        __syncthreads();
        sel ^= 1;
    }
}

extern "C" void kernel_launch(void* const* d_in, const int* in_sizes, int n_in,
                              void* d_out, int out_size)
{
    const float* canonical = (const float*)d_in[0];
    const float* w1        = (const float*)d_in[1];
    const float* b1        = (const float*)d_in[2];
    const float* w2        = (const float*)d_in[3];
    const float* b2        = (const float*)d_in[4];
    const int*   th        = (const int*)d_in[6];
    const int*   tw        = (const int*)d_in[7];
    float* out = (float*)d_out;

    cudaFuncSetAttribute(hgq_all, cudaFuncAttributeMaxDynamicSharedMemorySize, SMEM_BYTES);
    hgq_all<<<GRIDMAIN, TPB, SMEM_BYTES>>>(canonical, w1, b1, w2, b2, th, tw,
                                           out, out_size);
}

// round 12
// speedup vs baseline: 1.1600x; 1.1600x over previous
#include <cuda_runtime.h>
#include <cstdint>

// ---------------- problem constants ----------------
#define BATCH   64
#define MAXH    64
#define MAXW    32
#define DIM     512
#define SGRID   8
#define HID     64

#define TPB       256
#define GRIDMAIN  444      // 3 CTAs/SM x 148 SMs — ALL resident (global barrier safe)
#define TSTRIDE   111      // GRIDMAIN / 4 quarters
#define QELEMS    (BATCH * MAXH * MAXW * DIM)
#define NROWS     (BATCH * MAXH)          // 4096 (b,i) row units

// SMEM layout (bytes) — quarter-N, point-packed GEMM
#define HT_STRIDE 68       // padded floats per k-row (16B-aligned, conflict-free)
#define OFF_W2    0        // w2 quarter fp32 [64 k][128 d]          (32768)
#define OFF_HA    32768    // h_t buf0 [64 k][68] fp32               (17408)
#define OFF_HB    50176    // h_t buf1                               (17408)
#define OFF_B2    67584    // b2 quarter [128] fp32                  (512)
#define OFF_M0    68096    // meta buf0 (phase A: s_u/s_v)           (1024)
#define OFF_M1    69120    // meta buf1                              (1024)
#define OFF_BASE  70144    // s_base[65]                             (260)
#define OFF_HW    70404    // s_hw[64]                               (256)
#define OFF_W1U   70660
#define OFF_W1V   70916
#define OFF_B1    71172
#define SMEM_BYTES 71680   // <= ~75.7KB (227KB/3)

typedef unsigned long long ull;

// transposed compacted h: g_h[tile*4096 + k*64 + p]
__device__ __align__(16) float g_h[BATCH * MAXH * MAXW * HID];
__device__ unsigned g_bar = 0;     // rolling global barrier counter

__device__ __forceinline__ float gelu_exact(float x) {
    return 0.5f * x * (1.0f + erff(x * 0.70710678118654752440f));
}

__device__ __forceinline__ ull dupf(float x) {
    ull r;
    unsigned xb = __float_as_uint(x);
    asm("mov.b64 %0, {%1, %1};" : "=l"(r) : "r"(xb));
    return r;
}

// zero/mask one (b,i) row unit
__device__ __forceinline__ void do_row(
    int r, const int* s_hw, float* __restrict__ out,
    float* __restrict__ mout, int tail, int tid)
{
    const int b = r >> 6, i = r & 63;
    const int hw = s_hw[b];
    const int H = hw >> 16, W = hw & 0xFFFF;
    float4* row = (float4*)(out + ((size_t)r) * (MAXW * DIM));
    const float4 z = make_float4(0.f, 0.f, 0.f, 0.f);
    if (i >= H) {
        #pragma unroll
        for (int e = 0; e < (MAXW * DIM / 4) / TPB; e++)   // 16 iters
            row[tid + TPB * e] = z;
    } else if (W < MAXW) {
        int start4 = W * (DIM / 4);
        int cnt4 = (MAXW - W) * (DIM / 4);
        for (int e = tid; e < cnt4; e += TPB)
            row[start4 + e] = z;
    }
    if (tail > 0 && tid < 32) {
        int idx = r * 32 + tid;
        if (idx < tail)
            mout[idx] = (i < H && tid < W) ? 1.0f : 0.0f;
    }
}

// ---------------- single fused persistent kernel ----------------
__global__ __launch_bounds__(TPB, 3) void hgq_all(
    const float* __restrict__ canonical,   // [8,8,512]
    const float* __restrict__ w1,          // [2,64]
    const float* __restrict__ b1,          // [64]
    const float* __restrict__ w2,          // [64,512]
    const float* __restrict__ b2,          // [512]
    const int*   __restrict__ th,
    const int*   __restrict__ tw,
    float*       __restrict__ out,         // [64,64,32,512] (+ mask tail)
    int          out_size)
{
    extern __shared__ char smem[];
    int*   s_base = (int*)(smem + OFF_BASE);   // [65]
    int*   s_hw   = (int*)(smem + OFF_HW);     // [64]
    float* s_w1u  = (float*)(smem + OFF_W1U);
    float* s_w1v  = (float*)(smem + OFF_W1V);
    float* s_b1   = (float*)(smem + OFF_B1);
    volatile unsigned* s_tgt = (unsigned*)(smem + OFF_M1); // scratch for barrier target

    const int tid  = threadIdx.x;
    const int wid  = tid >> 5;
    const int nx   = tid & 31;
    const int qtr  = blockIdx.x & 3;
    const int t0   = blockIdx.x >> 2;
    const int tail = out_size - QELEMS;
    float* mout = out + QELEMS;

    // ---- one-time staging ----
    {
        const float* wsrc = w2 + qtr * 128;
        float4* ws = (float4*)(smem + OFF_W2);
        #pragma unroll
        for (int e = 0; e < 8; e++) {                  // 2048 float4
            int idx = tid + TPB * e;
            int k = idx >> 5, c4 = idx & 31;
            ws[idx] = __ldg((const float4*)(wsrc + k * DIM) + c4);
        }
        if (tid < 32)
            ((float4*)(smem + OFF_B2))[tid] = __ldg((const float4*)(b2 + qtr * 128) + tid);
        if (tid < 64) {
            s_w1u[tid] = __ldg(w1 + tid);
            s_w1v[tid] = __ldg(w1 + HID + tid);
            s_b1[tid]  = __ldg(b1 + tid);
            int H = min(max(__ldg(th + tid), 1), MAXH);
            int W = min(max(__ldg(tw + tid), 1), MAXW);
            s_hw[tid] = (H << 16) | W;
        }
    }
    __syncthreads();

    if (wid == 0) {
        int hw0 = s_hw[2 * nx], hw1 = s_hw[2 * nx + 1];
        int c0 = (hw0 >> 16) * (hw0 & 0xFFFF);
        int c1 = (hw1 >> 16) * (hw1 & 0xFFFF);
        int pair = c0 + c1, incl = pair;
        #pragma unroll
        for (int d = 1; d < 32; d <<= 1) {
            int n = __shfl_up_sync(0xFFFFFFFF, incl, d);
            if (nx >= d) incl += n;
        }
        s_base[2 * nx] = incl - pair;
        s_base[2 * nx + 1] = incl - c1;
        if (nx == 31) s_base[64] = incl;
    }
    __syncthreads();
    const int total = s_base[BATCH];

    // ============ PHASE A: gelu table, written TRANSPOSED [tile][k][p] ============
    {
        float* s_u = (float*)(smem + OFF_M0);
        float* s_v = (float*)(smem + OFF_M0 + 256);
        for (int tt = blockIdx.x; tt * 64 < total; tt += GRIDMAIN) {
            // step 1: u,v for the 64 points of this tile
            if (tid < 64) {
                int q = tt * 64 + tid;
                float u = 0.f, v = 0.f;
                if (q < total) {
                    int lo = 0, hi = BATCH;
                    while (hi - lo > 1) {
                        int mid = (lo + hi) >> 1;
                        if (q >= s_base[mid]) lo = mid; else hi = mid;
                    }
                    int hw = s_hw[lo];
                    int H = hw >> 16, W = hw & 0xFFFF;
                    int r = q - s_base[lo];
                    int i = r / W, j = r - i * W;
                    u = (H > 1) ? (float)i / (float)(H - 1) : 0.0f;
                    v = (W > 1) ? (float)j / (float)(W - 1) : 0.0f;
                }
                s_u[tid] = u; s_v[tid] = v;
            }
            __syncthreads();
            // step 2: thread (k = tid>>2, pg = tid&3) computes 16 points at one k
            {
                int k = tid >> 2, pg = tid & 3;
                float wu = s_w1u[k], wv = s_w1v[k], bk = s_b1[k];
                float* dst = g_h + (size_t)tt * 4096 + k * 64 + pg * 16;
                #pragma unroll
                for (int e = 0; e < 4; e++) {
                    float4 o;
                    int p = pg * 16 + e * 4;
                    o.x = gelu_exact(s_u[p + 0] * wu + s_v[p + 0] * wv + bk);
                    o.y = gelu_exact(s_u[p + 1] * wu + s_v[p + 1] * wv + bk);
                    o.z = gelu_exact(s_u[p + 2] * wu + s_v[p + 2] * wv + bk);
                    o.w = gelu_exact(s_u[p + 3] * wu + s_v[p + 3] * wv + bk);
                    *(float4*)(dst + e * 4) = o;
                }
            }
            __syncthreads();
        }
    }

    // ---- global barrier: release g_h, wait for all CTAs ----
    __threadfence();
    __syncthreads();
    if (tid == 0) {
        unsigned old = atomicAdd(&g_bar, 1u);
        s_tgt[0] = (old / GRIDMAIN + 1u) * GRIDMAIN;
    }
    __syncthreads();
    const unsigned bar_target = s_tgt[0];
    if (tid == 0) {
        unsigned v;
        do {
            asm volatile("ld.global.acquire.gpu.u32 %0, [%1];"
                         : "=r"(v) : "l"(&g_bar) : "memory");
            if (v >= bar_target) break;
            __nanosleep(64);
        } while (true);
    }
    __syncthreads();

    // ============ PHASE B: point-packed GEMM + epilogue + interleaved zero ============
    auto build = [&](int t, int sel) {
        float* ht = (float*)(smem + (sel ? OFF_HB : OFF_HA));
        char* mb = smem + (sel ? OFF_M1 : OFF_M0);
        int*   m_geom = (int*)mb;
        int*   m_addr = (int*)(mb + 256);
        float* m_wy   = (float*)(mb + 512);
        float* m_wx   = (float*)(mb + 768);

        // stream transposed h tile: 1024 float4, repack to padded stride
        const float4* src = (const float4*)(g_h + (size_t)t * 4096);
        #pragma unroll
        for (int e = 0; e < 4; e++) {
            int idx = tid + TPB * e;             // float4 index
            float4 v = src[idx];
            int k = idx >> 4, p4 = idx & 15;
            *(float4*)(ht + k * HT_STRIDE + p4 * 4) = v;
        }

        if (tid < 64) {
            int q = t * 64 + tid;
            if (q < total) {
                int lo = 0, hi = BATCH;
                while (hi - lo > 1) {
                    int mid = (lo + hi) >> 1;
                    if (q >= s_base[mid]) lo = mid; else hi = mid;
                }
                int b = lo;
                int hw = s_hw[b];
                int H = hw >> 16, W = hw & 0xFFFF;
                int r = q - s_base[b];
                int i = r / W, j = r - i * W;
                float u = (H > 1) ? (float)i / (float)(H - 1) : 0.0f;
                float v = (W > 1) ? (float)j / (float)(W - 1) : 0.0f;
                float sy = fminf(u * (float)(SGRID - 1), (float)(SGRID - 1));
                float sx = fminf(v * (float)(SGRID - 1), (float)(SGRID - 1));
                int y0 = (int)sy, x0 = (int)sx;
                int y1 = min(y0 + 1, SGRID - 1);
                int x1 = min(x0 + 1, SGRID - 1);
                m_wy[tid] = sy - (float)y0;
                m_wx[tid] = sx - (float)x0;
                m_geom[tid] = y0 | (y1 << 8) | (x0 << 16) | (x1 << 24);
                m_addr[tid] = (b << 11) | (i << 5) | j;
            } else {
                m_wy[tid] = 0.f; m_wx[tid] = 0.f;
                m_geom[tid] = 0;
                m_addr[tid] = -1;
            }
        }
    };

    int zr = blockIdx.x;       // zero/mask row cursor

    if (t0 * 64 < total) build(t0, 0);
    __syncthreads();

    int sel = 0;
    for (int t = t0; t * 64 < total; t += TSTRIDE) {
        const float* ht = (const float*)(smem + (sel ? OFF_HB : OFF_HA));
        const char* mb = smem + (sel ? OFF_M1 : OFF_M0);
        const int*   m_geom = (const int*)mb;
        const int*   m_addr = (const int*)(mb + 256);
        const float* m_wy   = (const float*)(mb + 512);
        const float* m_wx   = (const float*)(mb + 768);

        // ---- GEMM: acc[pi][dd] = {out[p0][d], out[p1][d]} ----
        ull acc[4][4];
        #pragma unroll
        for (int pi = 0; pi < 4; pi++)
            #pragma unroll
            for (int dd = 0; dd < 4; dd++) acc[pi][dd] = 0ull;

        const float* w2s = (const float*)(smem + OFF_W2);
        const int dlane = 4 * nx;                 // 4 contiguous d per thread

        #pragma unroll 4
        for (int k = 0; k < HID; k++) {
            float4 wq = *(const float4*)(w2s + k * 128 + dlane);
            ull wd0 = dupf(wq.x), wd1 = dupf(wq.y), wd2 = dupf(wq.z), wd3 = dupf(wq.w);
            const ulonglong2* hp = (const ulonglong2*)(ht + k * HT_STRIDE + 8 * wid);
            ulonglong2 hA = hp[0], hB = hp[1];    // point-pairs 0,1,2,3 (broadcast)
            ull ph0 = hA.x, ph1 = hA.y, ph2 = hB.x, ph3 = hB.y;
            #define FF(pi, ph) \
                asm("fma.rn.f32x2 %0, %1, %2, %3;" : "=l"(acc[pi][0]) : "l"(ph), "l"(wd0), "l"(acc[pi][0])); \
                asm("fma.rn.f32x2 %0, %1, %2, %3;" : "=l"(acc[pi][1]) : "l"(ph), "l"(wd1), "l"(acc[pi][1])); \
                asm("fma.rn.f32x2 %0, %1, %2, %3;" : "=l"(acc[pi][2]) : "l"(ph), "l"(wd2), "l"(acc[pi][2])); \
                asm("fma.rn.f32x2 %0, %1, %2, %3;" : "=l"(acc[pi][3]) : "l"(ph), "l"(wd3), "l"(acc[pi][3]));
            FF(0, ph0) FF(1, ph1) FF(2, ph2) FF(3, ph3)
            #undef FF
        }

        // ---- epilogue: per point, bilinear + unpacked acc + b2, STG.128 ----
        {
            const float4 b2v = *(const float4*)((const float*)(smem + OFF_B2) + dlane);
            const float* canq = canonical + qtr * 128 + dlane;
            const int pbase = wid * 8;

            #pragma unroll
            for (int pi = 0; pi < 4; pi++) {
                #pragma unroll
                for (int hlf = 0; hlf < 2; hlf++) {
                    int p = pbase + 2 * pi + hlf;
                    int ad = m_addr[p];
                    if (ad < 0) continue;
                    int geom = m_geom[p];
                    int y0 = geom & 0xFF, y1 = (geom >> 8) & 0xFF;
                    int x0 = (geom >> 16) & 0xFF, x1 = (geom >> 24) & 0xFF;
                    float wy = m_wy[p], wx = m_wx[p];
                    float4 q00 = __ldg((const float4*)(canq + (y0 * SGRID + x0) * DIM));
                    float4 q01 = __ldg((const float4*)(canq + (y0 * SGRID + x1) * DIM));
                    float4 q10 = __ldg((const float4*)(canq + (y1 * SGRID + x0) * DIM));
                    float4 q11 = __ldg((const float4*)(canq + (y1 * SGRID + x1) * DIM));
                    float w00 = (1.f - wy) * (1.f - wx), w01 = (1.f - wy) * wx;
                    float w10 = wy * (1.f - wx),         w11 = wy * wx;
                    float a0, a1, a2, a3;
                    if (hlf == 0) {
                        a0 = __uint_as_float((unsigned)acc[pi][0]);
                        a1 = __uint_as_float((unsigned)acc[pi][1]);
                        a2 = __uint_as_float((unsigned)acc[pi][2]);
                        a3 = __uint_as_float((unsigned)acc[pi][3]);
                    } else {
                        a0 = __uint_as_float((unsigned)(acc[pi][0] >> 32));
                        a1 = __uint_as_float((unsigned)(acc[pi][1] >> 32));
                        a2 = __uint_as_float((unsigned)(acc[pi][2] >> 32));
                        a3 = __uint_as_float((unsigned)(acc[pi][3] >> 32));
                    }
                    float4 r;
                    r.x = w00 * q00.x + w01 * q01.x + w10 * q10.x + w11 * q11.x + a0 + b2v.x;
                    r.y = w00 * q00.y + w01 * q01.y + w10 * q10.y + w11 * q11.y + a1 + b2v.y;
                    r.z = w00 * q00.z + w01 * q01.z + w10 * q10.z + w11 * q11.z + a2 + b2v.z;
                    r.w = w00 * q00.w + w01 * q01.w + w10 * q10.w + w11 * q11.w + a3 + b2v.w;
                    *(float4*)(out + (size_t)ad * DIM + qtr * 128 + dlane) = r;
                }
            }
        }

        // ---- build next tile, then interleaved zero/mask rows ----
        if ((t + TSTRIDE) * 64 < total) build(t + TSTRIDE, sel ^ 1);

        #pragma unroll 1
        for (int z = 0; z < 3 && zr < NROWS; z++, zr += GRIDMAIN)
            do_row(zr, s_hw, out, mout, tail, tid);

        __syncthreads();
        sel ^= 1;
    }

    // ---- remaining zero/mask rows ----
    #pragma unroll 1
    while (zr < NROWS) { do_row(zr, s_hw, out, mout, tail, tid); zr += GRIDMAIN; }

    // ---- padding past mask region (CTA 0) ----
    if (blockIdx.x == 0 && tail > NROWS * 32) {
        for (int e = NROWS * 32 + tid; e < tail; e += TPB)
            mout[e] = 0.0f;
    }
}

extern "C" void kernel_launch(void* const* d_in, const int* in_sizes, int n_in,
                              void* d_out, int out_size)
{
    const float* canonical = (const float*)d_in[0];
    const float* w1        = (const float*)d_in[1];
    const float* b1        = (const float*)d_in[2];
    const float* w2        = (const float*)d_in[3];
    const float* b2        = (const float*)d_in[4];
    const int*   th        = (const int*)d_in[6];
    const int*   tw        = (const int*)d_in[7];
    float* out = (float*)d_out;

    cudaFuncSetAttribute(hgq_all, cudaFuncAttributeMaxDynamicSharedMemorySize, SMEM_BYTES);
    hgq_all<<<GRIDMAIN, TPB, SMEM_BYTES>>>(canonical, w1, b1, w2, b2, th, tw,
                                           out, out_size);
}